// round 4
// baseline (speedup 1.0000x reference)
#include <cuda_runtime.h>
#include <cuda_fp16.h>

// SpectrumEncoding: out[b,d] = sum_n pe[ceil(loc[b,n]*10), d] * inten[b,n]
// B=1024, N=500, D=512.
//
// R3 finding: fp16 table cut L2 traffic to 525MB but gather became
// issue/latency-bound (L2 50.8%, fma 41%, issue 56%) at 45us.
// R4: 16B loads (64 thr/row, 2 rows/CTA) + packed fma.rn.f32x2 halve the
// per-byte instruction cost -> back to L2-byte-bound (~31us floor).

#define N_PEAKS    500
#define D_MODEL    512
#define RESO       10.0f
#define TABLE_ROWS 30001
#define ROW_U4     (D_MODEL / 8)      // 64 uint4 (8 halves each) per row

// fp16 copy of pe, rebuilt each call. 30.7 MB.
__device__ uint4 g_peh[TABLE_ROWS * ROW_U4];

// ---- packed f32x2 helpers (Blackwell FFMA2) --------------------------------
__device__ __forceinline__ unsigned long long pack2(float lo, float hi) {
    unsigned long long r;
    asm("mov.b64 %0, {%1, %2};" : "=l"(r) : "f"(lo), "f"(hi));
    return r;
}
__device__ __forceinline__ void unpack2(unsigned long long v, float& lo, float& hi) {
    asm("mov.b64 {%0, %1}, %2;" : "=f"(lo), "=f"(hi) : "l"(v));
}
__device__ __forceinline__ unsigned long long fma2(unsigned long long a,
                                                   unsigned long long b,
                                                   unsigned long long c) {
    unsigned long long d;
    asm("fma.rn.f32x2 %0, %1, %2, %3;" : "=l"(d) : "l"(a), "l"(b), "l"(c));
    return d;
}

// ---------------------------------------------------------------------------
// Pass 1: f32 -> f16, 32B reads / 16B writes per thread.
// ---------------------------------------------------------------------------
__global__ void convert_pe_kernel(const float4* __restrict__ pe4)
{
    const int total = TABLE_ROWS * ROW_U4;         // 1,920,064 uint4 outputs
    for (int i = blockIdx.x * blockDim.x + threadIdx.x;
         i < total;
         i += gridDim.x * blockDim.x) {
        float4 a = pe4[2 * i];
        float4 b = pe4[2 * i + 1];
        __half2 h0 = __floats2half2_rn(a.x, a.y);
        __half2 h1 = __floats2half2_rn(a.z, a.w);
        __half2 h2 = __floats2half2_rn(b.x, b.y);
        __half2 h3 = __floats2half2_rn(b.z, b.w);
        uint4 p;
        p.x = *reinterpret_cast<unsigned*>(&h0);
        p.y = *reinterpret_cast<unsigned*>(&h1);
        p.z = *reinterpret_cast<unsigned*>(&h2);
        p.w = *reinterpret_cast<unsigned*>(&h3);
        g_peh[i] = p;
    }
}

// ---------------------------------------------------------------------------
// Pass 2: gather + weighted reduce.
// CTA = 128 threads = 2 batch rows x 64 threads. Thread t64 owns output
// floats [8*t64, 8*t64+8) of its row = one uint4 (8 halves) per gather.
// Warps 0-1 -> row A, warps 2-3 -> row B: s_w reads are warp-broadcast.
// ---------------------------------------------------------------------------
__global__ __launch_bounds__(128)
void SpectrumEncoding_kernel(const float*  __restrict__ loc,
                             const float*  __restrict__ inten,
                             float4*       __restrict__ out4)
{
    __shared__ int   s_idx[2][N_PEAKS];   // premultiplied: row * ROW_U4
    __shared__ float s_w[2][N_PEAKS];

    const int t   = threadIdx.x;
    const int r   = t >> 6;               // row within CTA (0/1)
    const int t64 = t & 63;
    const int b0  = blockIdx.x * 2;

    #pragma unroll
    for (int rr = 0; rr < 2; ++rr) {
        const float* lrow = loc   + (long long)(b0 + rr) * N_PEAKS;
        const float* irow = inten + (long long)(b0 + rr) * N_PEAKS;
        for (int n = t; n < N_PEAKS; n += 128) {
            s_idx[rr][n] = ((int)ceilf(lrow[n] * RESO)) * ROW_U4;
            s_w[rr][n]   = irow[n];
        }
    }
    __syncthreads();

    // 4 packed f32x2 accumulators = 8 floats. 0ull == {0.f, 0.f}.
    unsigned long long acc0 = 0ull, acc1 = 0ull, acc2 = 0ull, acc3 = 0ull;

    #pragma unroll 8
    for (int n = 0; n < N_PEAKS; ++n) {
        const float w = s_w[r][n];
        const uint4 v = __ldg(&g_peh[s_idx[r][n] + t64]);
        const unsigned long long w2 = pack2(w, w);

        const __half2 h0 = *reinterpret_cast<const __half2*>(&v.x);
        const __half2 h1 = *reinterpret_cast<const __half2*>(&v.y);
        const __half2 h2 = *reinterpret_cast<const __half2*>(&v.z);
        const __half2 h3 = *reinterpret_cast<const __half2*>(&v.w);
        const float2 f0 = __half22float2(h0);
        const float2 f1 = __half22float2(h1);
        const float2 f2 = __half22float2(h2);
        const float2 f3 = __half22float2(h3);

        acc0 = fma2(pack2(f0.x, f0.y), w2, acc0);
        acc1 = fma2(pack2(f1.x, f1.y), w2, acc1);
        acc2 = fma2(pack2(f2.x, f2.y), w2, acc2);
        acc3 = fma2(pack2(f3.x, f3.y), w2, acc3);
    }

    float4 o0, o1;
    unpack2(acc0, o0.x, o0.y);
    unpack2(acc1, o0.z, o0.w);
    unpack2(acc2, o1.x, o1.y);
    unpack2(acc3, o1.z, o1.w);

    float4* orow = out4 + (long long)(b0 + r) * (D_MODEL / 4);
    orow[2 * t64]     = o0;
    orow[2 * t64 + 1] = o1;
}

extern "C" void kernel_launch(void* const* d_in, const int* in_sizes, int n_in,
                              void* d_out, int out_size)
{
    const float*  loc   = (const float*)d_in[0];   // [B, 500]
    const float*  inten = (const float*)d_in[1];   // [B, 500]
    const float4* pe4   = (const float4*)d_in[2];  // [30001, 512] f32
    float4*       out4  = (float4*)d_out;          // [B, 512] f32

    const int B = in_sizes[0] / N_PEAKS;           // 1024

    convert_pe_kernel<<<960, 256>>>(pe4);
    SpectrumEncoding_kernel<<<B / 2, 128>>>(loc, inten, out4);
}

// round 5
// speedup vs baseline: 1.5867x; 1.5867x over previous
#include <cuda_runtime.h>
#include <cuda_fp16.h>

// SpectrumEncoding: out[b,d] = sum_n pe[ceil(loc[b,n]*10), d] * inten[b,n]
// B=1024, N=500, D=512.
//
// R3 (45us gather) was issue-bound at 56% issue / 32% occ (one 1024-CTA wave).
// R4 (inline-asm f32x2 + grid 512) collapsed MLP -> reverted.
// R5: R3 codegen (scalar fmaf, LDG.64, no asm) + peak-split across 2048 CTAs
// (250 peaks each -> disjoint partials, no atomics) + fused (idx,w) LDS.64.
// Partials reduced by a tiny second kernel.

#define N_PEAKS    500
#define HALF_PEAKS 250
#define D_MODEL    512
#define RESO       10.0f
#define TABLE_ROWS 30001
#define ROW_U2     (D_MODEL / 4)     // 128 x 8B (4 halves) per fp16 row

// fp16 copy of pe, rebuilt each call (30.7 MB).
__device__ uint2 g_peh[TABLE_ROWS * ROW_U2];
// per-(row,half) partial sums: [1024*2][512] f32 = 4 MB
__device__ float4 g_partial[2048 * (D_MODEL / 4)];

// ---------------------------------------------------------------------------
// Pass 1: f32 -> f16 conversion. 32B read / 16B write per thread.
// Both tables fit L2 together (92MB) -> L2-bound in steady state.
// ---------------------------------------------------------------------------
__global__ void convert_pe_kernel(const float4* __restrict__ pe4)
{
    uint4* __restrict__ dst = reinterpret_cast<uint4*>(g_peh);
    const int total = TABLE_ROWS * ROW_U2 / 2;     // 1,920,064 uint4
    for (int i = blockIdx.x * blockDim.x + threadIdx.x;
         i < total;
         i += gridDim.x * blockDim.x) {
        float4 a = pe4[2 * i];
        float4 b = pe4[2 * i + 1];
        __half2 h0 = __floats2half2_rn(a.x, a.y);
        __half2 h1 = __floats2half2_rn(a.z, a.w);
        __half2 h2 = __floats2half2_rn(b.x, b.y);
        __half2 h3 = __floats2half2_rn(b.z, b.w);
        uint4 p;
        p.x = *reinterpret_cast<unsigned*>(&h0);
        p.y = *reinterpret_cast<unsigned*>(&h1);
        p.z = *reinterpret_cast<unsigned*>(&h2);
        p.w = *reinterpret_cast<unsigned*>(&h3);
        dst[i] = p;
    }
}

// ---------------------------------------------------------------------------
// Pass 2: gather + weighted partial reduce.
// CTA = (batch row, peak half). 128 threads, thread t owns one uint2
// (4 halves) of the fp16 row -> float4 of the output. 250 iterations.
// ---------------------------------------------------------------------------
__global__ __launch_bounds__(128)
void SpectrumEncoding_kernel(const float*  __restrict__ loc,
                             const float*  __restrict__ inten)
{
    __shared__ float2 s_iw[HALF_PEAKS];   // .x = idx*ROW_U2 as int bits, .y = w

    const int cta  = blockIdx.x;          // 0..2047
    const int b    = cta >> 1;
    const int nbeg = (cta & 1) * HALF_PEAKS;
    const int t    = threadIdx.x;

    const float* lrow = loc   + (long long)b * N_PEAKS + nbeg;
    const float* irow = inten + (long long)b * N_PEAKS + nbeg;

    for (int n = t; n < HALF_PEAKS; n += 128) {
        int idx = (int)ceilf(lrow[n] * RESO);
        s_iw[n] = make_float2(__int_as_float(idx * ROW_U2), irow[n]);
    }
    __syncthreads();

    float4 acc = make_float4(0.f, 0.f, 0.f, 0.f);

    #pragma unroll 10
    for (int n = 0; n < HALF_PEAKS; ++n) {
        const float2 iw = s_iw[n];
        const float  w  = iw.y;
        const uint2  v  = __ldg(&g_peh[__float_as_int(iw.x) + t]);
        const float2 f0 = __half22float2(*reinterpret_cast<const __half2*>(&v.x));
        const float2 f1 = __half22float2(*reinterpret_cast<const __half2*>(&v.y));
        acc.x = fmaf(w, f0.x, acc.x);
        acc.y = fmaf(w, f0.y, acc.y);
        acc.z = fmaf(w, f1.x, acc.z);
        acc.w = fmaf(w, f1.y, acc.w);
    }

    g_partial[cta * ROW_U2 + t] = acc;
}

// ---------------------------------------------------------------------------
// Pass 3: add the two peak-half partials per row. 6MB traffic.
// ---------------------------------------------------------------------------
__global__ void reduce_kernel(float4* __restrict__ out4)
{
    const int total = 1024 * ROW_U2;      // 131072 float4 outputs
    int i = blockIdx.x * blockDim.x + threadIdx.x;
    if (i >= total) return;
    const int b = i / ROW_U2;
    const int t = i - b * ROW_U2;
    float4 p0 = g_partial[(2 * b)     * ROW_U2 + t];
    float4 p1 = g_partial[(2 * b + 1) * ROW_U2 + t];
    out4[i] = make_float4(p0.x + p1.x, p0.y + p1.y,
                          p0.z + p1.z, p0.w + p1.w);
}

extern "C" void kernel_launch(void* const* d_in, const int* in_sizes, int n_in,
                              void* d_out, int out_size)
{
    const float*  loc   = (const float*)d_in[0];   // [B, 500]
    const float*  inten = (const float*)d_in[1];   // [B, 500]
    const float4* pe4   = (const float4*)d_in[2];  // [30001, 512] f32
    float4*       out4  = (float4*)d_out;          // [B, 512] f32

    const int B = in_sizes[0] / N_PEAKS;           // 1024

    convert_pe_kernel<<<1024, 256>>>(pe4);
    SpectrumEncoding_kernel<<<B * 2, 128>>>(loc, inten);
    reduce_kernel<<<(1024 * ROW_U2 + 255) / 256, 256>>>(out4);
}

// round 7
// speedup vs baseline: 1.6592x; 1.0456x over previous
#include <cuda_runtime.h>
#include <cuda_fp16.h>

// SpectrumEncoding: out[b,d] = sum_n pe[ceil(loc[b,n]*10), d] * inten[b,n]
// B=1024, N=500, D=512.
//
// R5 finding: fp16 gather pinned ~43us by LSU dispatch count (same #LDG as
// f32), not L2 bytes or issue slots. R6: LDG.128 on the fp16 table halves
// warp-LDG count (2 peaks/iter, 2x64-thread groups per CTA), peak-split grid
// 2048 for occupancy, unrolled convert pass. Floors: LSU ~14us, issue ~15us,
// L2 525MB ~24us -> gather should be L2-byte-bound.
// (R6 bench was an infra failure; this is an identical resubmit.)

#define N_PEAKS    500
#define HALF_PEAKS 250
#define N_ITERS    125           // 2 peaks per iteration
#define D_MODEL    512
#define RESO       10.0f
#define TABLE_ROWS 30001
#define ROW_U4     (D_MODEL / 8) // 64 uint4 (8 halves) per fp16 row

// fp16 copy of pe, rebuilt each call (30.7 MB).
__device__ uint4 g_peh[TABLE_ROWS * ROW_U4];
// per-(row,half) partial sums: [2048][512] f32 = 4 MB
__device__ float4 g_partial[2048 * (D_MODEL / 4)];

// ---------------------------------------------------------------------------
// Pass 1: f32 -> f16. Coalesced float4 read -> uint2 write, 4 independent
// loads in flight per thread (grid-stride, unroll 4).
// ---------------------------------------------------------------------------
__global__ void convert_pe_kernel(const float4* __restrict__ pe4)
{
    uint2* __restrict__ dst = reinterpret_cast<uint2*>(g_peh);
    const int total  = TABLE_ROWS * (D_MODEL / 4);   // 3,840,128 uint2 outputs
    const int stride = gridDim.x * blockDim.x;

    for (int i = blockIdx.x * blockDim.x + threadIdx.x;
         i < total;
         i += 4 * stride) {
        #pragma unroll 4
        for (int j = 0; j < 4; ++j) {
            const int k = i + j * stride;
            if (k < total) {
                float4 v = pe4[k];
                __half2 h0 = __floats2half2_rn(v.x, v.y);
                __half2 h1 = __floats2half2_rn(v.z, v.w);
                uint2 p;
                p.x = *reinterpret_cast<unsigned*>(&h0);
                p.y = *reinterpret_cast<unsigned*>(&h1);
                dst[k] = p;
            }
        }
    }
}

// ---------------------------------------------------------------------------
// Pass 2: gather + weighted partial reduce.
// CTA = (batch row, peak half): 250 peaks. 128 threads = 2 groups of 64;
// group g handles peak 2*it+g each iteration with one LDG.128 (8 halves)
// per thread. Group accumulators combined via smem; CTA writes its partial.
// ---------------------------------------------------------------------------
__global__ __launch_bounds__(128)
void SpectrumEncoding_kernel(const float*  __restrict__ loc,
                             const float*  __restrict__ inten)
{
    __shared__ float2 s_iw[HALF_PEAKS];  // .x = idx*ROW_U4 as int bits, .y = w
    __shared__ float4 s_red[128];        // group-1 accumulators (2 KB)

    const int cta  = blockIdx.x;         // 0..2047
    const int b    = cta >> 1;
    const int nbeg = (cta & 1) * HALF_PEAKS;
    const int t    = threadIdx.x;
    const int g    = t >> 6;             // thread-group 0/1 (2 warps each)
    const int t64  = t & 63;

    const float* lrow = loc   + (long long)b * N_PEAKS + nbeg;
    const float* irow = inten + (long long)b * N_PEAKS + nbeg;

    for (int n = t; n < HALF_PEAKS; n += 128) {
        int idx = (int)ceilf(lrow[n] * RESO);
        s_iw[n] = make_float2(__int_as_float(idx * ROW_U4), irow[n]);
    }
    __syncthreads();

    float4 a0 = make_float4(0.f, 0.f, 0.f, 0.f);
    float4 a1 = make_float4(0.f, 0.f, 0.f, 0.f);

    #pragma unroll 5
    for (int it = 0; it < N_ITERS; ++it) {
        const float2 iw = s_iw[2 * it + g];          // warp-uniform broadcast
        const float  w  = iw.y;
        const uint4  v  = __ldg(&g_peh[__float_as_int(iw.x) + t64]);
        const float2 f0 = __half22float2(*reinterpret_cast<const __half2*>(&v.x));
        const float2 f1 = __half22float2(*reinterpret_cast<const __half2*>(&v.y));
        const float2 f2 = __half22float2(*reinterpret_cast<const __half2*>(&v.z));
        const float2 f3 = __half22float2(*reinterpret_cast<const __half2*>(&v.w));
        a0.x = fmaf(w, f0.x, a0.x);
        a0.y = fmaf(w, f0.y, a0.y);
        a0.z = fmaf(w, f1.x, a0.z);
        a0.w = fmaf(w, f1.y, a0.w);
        a1.x = fmaf(w, f2.x, a1.x);
        a1.y = fmaf(w, f2.y, a1.y);
        a1.z = fmaf(w, f3.x, a1.z);
        a1.w = fmaf(w, f3.y, a1.w);
    }

    // Combine the two peak-groups, then write this CTA's partial row.
    if (g == 1) {
        s_red[t64]      = a0;
        s_red[64 + t64] = a1;
    }
    __syncthreads();
    if (g == 0) {
        const float4 b0 = s_red[t64];
        const float4 b1 = s_red[64 + t64];
        a0.x += b0.x; a0.y += b0.y; a0.z += b0.z; a0.w += b0.w;
        a1.x += b1.x; a1.y += b1.y; a1.z += b1.z; a1.w += b1.w;
        float4* prow = g_partial + (long long)cta * (D_MODEL / 4);
        prow[2 * t64]     = a0;
        prow[2 * t64 + 1] = a1;
    }
}

// ---------------------------------------------------------------------------
// Pass 3: add the two peak-half partials per batch row (6 MB, ~1.5us).
// ---------------------------------------------------------------------------
__global__ void reduce_kernel(float4* __restrict__ out4)
{
    const int total = 1024 * (D_MODEL / 4);          // 131072 float4
    int i = blockIdx.x * blockDim.x + threadIdx.x;
    if (i >= total) return;
    const int b = i >> 7;                            // / 128
    const int t = i & 127;
    float4 p0 = g_partial[(2 * b)     * (D_MODEL / 4) + t];
    float4 p1 = g_partial[(2 * b + 1) * (D_MODEL / 4) + t];
    out4[i] = make_float4(p0.x + p1.x, p0.y + p1.y,
                          p0.z + p1.z, p0.w + p1.w);
}

extern "C" void kernel_launch(void* const* d_in, const int* in_sizes, int n_in,
                              void* d_out, int out_size)
{
    const float*  loc   = (const float*)d_in[0];   // [B, 500]
    const float*  inten = (const float*)d_in[1];   // [B, 500]
    const float4* pe4   = (const float4*)d_in[2];  // [30001, 512] f32
    float4*       out4  = (float4*)d_out;          // [B, 512] f32

    const int B = in_sizes[0] / N_PEAKS;           // 1024

    convert_pe_kernel<<<2048, 256>>>(pe4);
    SpectrumEncoding_kernel<<<B * 2, 128>>>(loc, inten);
    reduce_kernel<<<(1024 * (D_MODEL / 4) + 255) / 256, 256>>>(out4);
}

// round 8
// speedup vs baseline: 1.8406x; 1.1094x over previous
#include <cuda_runtime.h>
#include <cuda_fp16.h>

// SpectrumEncoding: out[b,d] = sum_n pe[ceil(loc[b,n]*10), d] * inten[b,n]
// B=1024, N=500, D=512.
//
// R3/R5/R7 triangulation: gather time tracks TOTAL warp-instruction count
// (~2.0us per M instrs, issue ~55%), not load count, bytes, or occupancy.
// R8: halve the instruction count. w staged as half2, per-iter math = 4
// HFMA2 (fp16 accumulate), flushed to f32 every 5 peaks. ~10.5 instr/iter
// -> issue floor ~10us, L2-byte floor (525MB) ~27-31us becomes binding.

#define N_PEAKS    500
#define HALF_PEAKS 250
#define N_ITERS    125           // per group: 125 peaks, in 25 blocks of 5
#define D_MODEL    512
#define RESO       10.0f
#define TABLE_ROWS 30001
#define ROW_U4     (D_MODEL / 8) // 64 uint4 (8 halves) per fp16 row

// fp16 copy of pe, rebuilt each call (30.7 MB).
__device__ uint4 g_peh[TABLE_ROWS * ROW_U4];
// per-(row,half) partial sums: [2048][512] f32 = 4 MB
__device__ float4 g_partial[2048 * (D_MODEL / 4)];

// ---------------------------------------------------------------------------
// Pass 1: f32 -> f16. One 8-deep predicated unroll per thread (MLP=8).
// ---------------------------------------------------------------------------
__global__ void convert_pe_kernel(const float4* __restrict__ pe4)
{
    uint2* __restrict__ dst = reinterpret_cast<uint2*>(g_peh);
    const int total  = TABLE_ROWS * (D_MODEL / 4);   // 3,840,128 uint2
    const int stride = gridDim.x * blockDim.x;       // 524,288
    const int i0     = blockIdx.x * blockDim.x + threadIdx.x;

    #pragma unroll 8
    for (int j = 0; j < 8; ++j) {
        const int k = i0 + j * stride;
        if (k < total) {
            float4 v = pe4[k];
            __half2 h0 = __floats2half2_rn(v.x, v.y);
            __half2 h1 = __floats2half2_rn(v.z, v.w);
            uint2 p;
            p.x = *reinterpret_cast<unsigned*>(&h0);
            p.y = *reinterpret_cast<unsigned*>(&h1);
            dst[k] = p;
        }
    }
}

// ---------------------------------------------------------------------------
// Pass 2: gather + weighted partial reduce.
// CTA = (batch row, peak half): 250 peaks. 128 threads = 2 groups of 64;
// group g handles peak 2*it+g. fp16 HFMA2 accumulate in 5-peak blocks,
// flushed to f32 accumulators (precision: ~2.5e-4 aggregate rel err).
// ---------------------------------------------------------------------------
__global__ __launch_bounds__(128)
void SpectrumEncoding_kernel(const float*  __restrict__ loc,
                             const float*  __restrict__ inten)
{
    __shared__ float2 s_iw[HALF_PEAKS];  // .x = (idx*ROW_U4) bits, .y = half2(w,w) bits
    __shared__ float4 s_red[128];        // group-1 accumulators (2 KB)

    const int cta  = blockIdx.x;         // 0..2047
    const int b    = cta >> 1;
    const int nbeg = (cta & 1) * HALF_PEAKS;
    const int t    = threadIdx.x;
    const int g    = t >> 6;             // thread-group 0/1 (2 warps each)
    const int t64  = t & 63;

    const float* lrow = loc   + (long long)b * N_PEAKS + nbeg;
    const float* irow = inten + (long long)b * N_PEAKS + nbeg;

    for (int n = t; n < HALF_PEAKS; n += 128) {
        int idx = (int)ceilf(lrow[n] * RESO);
        __half2 w2 = __half2half2(__float2half(irow[n]));
        s_iw[n] = make_float2(__int_as_float(idx * ROW_U4),
                              __uint_as_float(*reinterpret_cast<unsigned*>(&w2)));
    }
    __syncthreads();

    float4 a0 = make_float4(0.f, 0.f, 0.f, 0.f);
    float4 a1 = make_float4(0.f, 0.f, 0.f, 0.f);

    for (int blk = 0; blk < 25; ++blk) {
        __half2 h0 = __half2half2(__ushort_as_half(0));
        __half2 h1 = h0, h2 = h0, h3 = h0;

        #pragma unroll
        for (int j = 0; j < 5; ++j) {
            const int n = (blk * 5 + j) * 2 + g;
            const float2 iw = s_iw[n];                 // warp-uniform broadcast
            const unsigned wb = __float_as_uint(iw.y);
            const __half2  w2 = *reinterpret_cast<const __half2*>(&wb);
            const uint4    v  = __ldg(&g_peh[__float_as_int(iw.x) + t64]);
            h0 = __hfma2(*reinterpret_cast<const __half2*>(&v.x), w2, h0);
            h1 = __hfma2(*reinterpret_cast<const __half2*>(&v.y), w2, h1);
            h2 = __hfma2(*reinterpret_cast<const __half2*>(&v.z), w2, h2);
            h3 = __hfma2(*reinterpret_cast<const __half2*>(&v.w), w2, h3);
        }

        const float2 f0 = __half22float2(h0);
        const float2 f1 = __half22float2(h1);
        const float2 f2 = __half22float2(h2);
        const float2 f3 = __half22float2(h3);
        a0.x += f0.x; a0.y += f0.y; a0.z += f1.x; a0.w += f1.y;
        a1.x += f2.x; a1.y += f2.y; a1.z += f3.x; a1.w += f3.y;
    }

    // Combine the two peak-groups, then write this CTA's partial row.
    if (g == 1) {
        s_red[t64]      = a0;
        s_red[64 + t64] = a1;
    }
    __syncthreads();
    if (g == 0) {
        const float4 b0 = s_red[t64];
        const float4 b1 = s_red[64 + t64];
        a0.x += b0.x; a0.y += b0.y; a0.z += b0.z; a0.w += b0.w;
        a1.x += b1.x; a1.y += b1.y; a1.z += b1.z; a1.w += b1.w;
        float4* prow = g_partial + (long long)cta * (D_MODEL / 4);
        prow[2 * t64]     = a0;
        prow[2 * t64 + 1] = a1;
    }
}

// ---------------------------------------------------------------------------
// Pass 3: add the two peak-half partials per batch row (6 MB, ~2us).
// ---------------------------------------------------------------------------
__global__ void reduce_kernel(float4* __restrict__ out4)
{
    const int total = 1024 * (D_MODEL / 4);          // 131072 float4
    int i = blockIdx.x * blockDim.x + threadIdx.x;
    if (i >= total) return;
    const int b = i >> 7;                            // / 128
    const int t = i & 127;
    float4 p0 = g_partial[(2 * b)     * (D_MODEL / 4) + t];
    float4 p1 = g_partial[(2 * b + 1) * (D_MODEL / 4) + t];
    out4[i] = make_float4(p0.x + p1.x, p0.y + p1.y,
                          p0.z + p1.z, p0.w + p1.w);
}

extern "C" void kernel_launch(void* const* d_in, const int* in_sizes, int n_in,
                              void* d_out, int out_size)
{
    const float*  loc   = (const float*)d_in[0];   // [B, 500]
    const float*  inten = (const float*)d_in[1];   // [B, 500]
    const float4* pe4   = (const float4*)d_in[2];  // [30001, 512] f32
    float4*       out4  = (float4*)d_out;          // [B, 512] f32

    const int B = in_sizes[0] / N_PEAKS;           // 1024

    convert_pe_kernel<<<2048, 256>>>(pe4);
    SpectrumEncoding_kernel<<<B * 2, 128>>>(loc, inten);
    reduce_kernel<<<(1024 * (D_MODEL / 4) + 255) / 256, 256>>>(out4);
}